// round 8
// baseline (speedup 1.0000x reference)
#include <cuda_runtime.h>
#include <cuda_bf16.h>
#include <math.h>

#define NN 50000
#define NE 800000
#define D  64
#define NC 8
#define CAP 64   // bucket capacity per node (deg ~ Poisson(16); P(>64) ~ 1e-18)

// ---------------- scratch (device globals; no allocation allowed) -----------
__device__ float g_deg[NN];                        // dinv after k_dinv
__device__ int   g_fill[NN];                       // bucket fill counter (in-degree)
__device__ __align__(16) int2  g_csr[NN * CAP];    // {src, bitcast(w->norm)} per in-edge
__device__ __align__(16) float g_h[NN * D];        // h = X @ W
__device__ __align__(16) float g_agg[NN * D];      // aggregated output

// ---------------- init: fill = 0 ---------------------------------------------
__global__ void k_init() {
    int i = blockIdx.x * blockDim.x + threadIdx.x;
    if (i < NN) g_fill[i] = 0;
}

// ---------------- bucket fill: {src, w}, 4 edges/thread (MLP=4) --------------
// edge_index is int32 (JAX x64 disabled => "int64" materializes as int32)
__global__ void k_fill(const int* __restrict__ ei, const float* __restrict__ w) {
    int base = (blockIdx.x * blockDim.x + threadIdx.x) * 4;   // NE % 4 == 0
    if (base >= NE) return;
    int4   s4 = *(const int4*)(ei + base);
    int4   d4 = *(const int4*)(ei + NE + base);
    float4 w4 = *(const float4*)(w + base);

    int p0 = atomicAdd(&g_fill[d4.x], 1);
    int p1 = atomicAdd(&g_fill[d4.y], 1);
    int p2 = atomicAdd(&g_fill[d4.z], 1);
    int p3 = atomicAdd(&g_fill[d4.w], 1);
    if (p0 < CAP) g_csr[d4.x * CAP + p0] = make_int2(s4.x, __float_as_int(w4.x));
    if (p1 < CAP) g_csr[d4.y * CAP + p1] = make_int2(s4.y, __float_as_int(w4.y));
    if (p2 < CAP) g_csr[d4.z * CAP + p2] = make_int2(s4.z, __float_as_int(w4.z));
    if (p3 < CAP) g_csr[d4.w * CAP + p3] = make_int2(s4.w, __float_as_int(w4.w));
}

// ---------------- dinv: one warp per node, sum bucket weights, rsqrt ---------
__global__ void __launch_bounds__(256) k_dinv() {
    int tid = threadIdx.x;
    int lane = tid & 31;
    int node = blockIdx.x * 8 + (tid >> 5);
    if (node >= NN) return;

    int cnt = min(g_fill[node], CAP);
    const int2* ent = g_csr + (size_t)node * CAP;
    float sum = 0.f;
#pragma unroll
    for (int base = 0; base < CAP; base += 32) {
        int k = base + lane;
        if (k < cnt) sum += __int_as_float(ent[k].y);
    }
#pragma unroll
    for (int off = 16; off > 0; off >>= 1)
        sum += __shfl_xor_sync(0xFFFFFFFF, sum, off);
    if (lane == 0)
        g_deg[node] = rsqrtf(1.0f + sum);          // self-loop weight 1
}

// ---------------- bnorm: rewrite bucket w -> norm in place -------------------
__global__ void __launch_bounds__(256) k_bnorm() {
    int tid = threadIdx.x;
    int lane = tid & 31;
    int node = blockIdx.x * 8 + (tid >> 5);
    if (node >= NN) return;

    int cnt = min(g_fill[node], CAP);
    float dd = g_deg[node];
    int2* ent = g_csr + (size_t)node * CAP;
    for (int k = lane; k < cnt; k += 32) {
        int2 e = ent[k];
        e.y = __float_as_int(g_deg[e.x] * __int_as_float(e.y) * dd);
        ent[k] = e;
    }
}

// ---------------- dense GEMM: Hout[node] = (relu?)(X[node]) @ W  ([64,64]) ---
// 4 threads per node; thread q computes outputs [q*16, q*16+16).
// acc = 4 float4 (16 regs) -> high occupancy vs the old 64-reg accumulator.
template <bool RELU>
__global__ void __launch_bounds__(256) k_gemm(const float* __restrict__ X,
                                              const float* __restrict__ W,
                                              float* __restrict__ Hout) {
    __shared__ float4 sW[D * (D / 4)];             // [k][j] 64x16 float4 = 16 KB
    int tid = threadIdx.x;
    for (int i = tid; i < D * (D / 4); i += 256)
        sW[i] = ((const float4*)W)[i];
    __syncthreads();

    int node = blockIdx.x * 64 + (tid >> 2);
    int q = tid & 3;
    if (node >= NN) return;

    const float4* xr = (const float4*)(X + (size_t)node * D);
    float4 acc[4];
#pragma unroll
    for (int j = 0; j < 4; j++) acc[j] = make_float4(0.f, 0.f, 0.f, 0.f);

#pragma unroll 4
    for (int kc = 0; kc < 16; kc++) {
        float4 xv = __ldg(&xr[kc]);
        if (RELU) {
            xv.x = fmaxf(xv.x, 0.f); xv.y = fmaxf(xv.y, 0.f);
            xv.z = fmaxf(xv.z, 0.f); xv.w = fmaxf(xv.w, 0.f);
        }
#pragma unroll
        for (int kk = 0; kk < 4; kk++) {
            float xs = (kk == 0) ? xv.x : (kk == 1) ? xv.y : (kk == 2) ? xv.z : xv.w;
            int k = kc * 4 + kk;
#pragma unroll
            for (int jj = 0; jj < 4; jj++) {
                float4 wv = sW[k * 16 + q * 4 + jj];
                acc[jj].x = fmaf(xs, wv.x, acc[jj].x);
                acc[jj].y = fmaf(xs, wv.y, acc[jj].y);
                acc[jj].z = fmaf(xs, wv.z, acc[jj].z);
                acc[jj].w = fmaf(xs, wv.w, acc[jj].w);
            }
        }
    }
    float4* ho = (float4*)(Hout + (size_t)node * D);
#pragma unroll
    for (int jj = 0; jj < 4; jj++) ho[q * 4 + jj] = acc[jj];
}

// ---------------- gather: agg[i] = h[i]*dinv^2 + b + sum_in norm * h[src] ---
// 16 threads per node; lane j owns float4 chunk j of the 64-wide row.
__global__ void __launch_bounds__(256) k_gather(const float* __restrict__ b) {
    int tid = threadIdx.x;
    int grp = tid >> 4;
    int j = tid & 15;
    int node = blockIdx.x * 16 + grp;
    if (node >= NN) return;

    int cnt = min(g_fill[node], CAP);
    float dinv = g_deg[node];
    float d2 = dinv * dinv;

    const float4* h4 = (const float4*)g_h;
    float4 acc = h4[(size_t)node * 16 + j];        // self-loop term
    float4 bb = ((const float4*)b)[j];
    acc.x = fmaf(acc.x, d2, bb.x);
    acc.y = fmaf(acc.y, d2, bb.y);
    acc.z = fmaf(acc.z, d2, bb.z);
    acc.w = fmaf(acc.w, d2, bb.w);

    const int2* ent = g_csr + (size_t)node * CAP;
#pragma unroll 4
    for (int k = 0; k < cnt; k++) {
        int2 e = ent[k];                            // broadcast across the 16 lanes
        float nrm = __int_as_float(e.y);            // precomputed norm
        float4 v = h4[(size_t)e.x * 16 + j];        // coalesced 256B row (L2 hit)
        acc.x = fmaf(nrm, v.x, acc.x);
        acc.y = fmaf(nrm, v.y, acc.y);
        acc.z = fmaf(nrm, v.z, acc.z);
        acc.w = fmaf(nrm, v.w, acc.w);
    }
    ((float4*)g_agg)[(size_t)node * 16 + j] = acc;
}

// ---------------- head: relu -> @Wm + bm -> softmax -------------------------
__global__ void __launch_bounds__(256) k_final(const float* __restrict__ Wm,
                                               const float* __restrict__ bm,
                                               float* __restrict__ out) {
    __shared__ float sWm[D * NC];
    __shared__ float sbm[NC];
    int tid = threadIdx.x;
    for (int i = tid; i < D * NC; i += 256) sWm[i] = Wm[i];
    if (tid < NC) sbm[tid] = bm[tid];
    __syncthreads();

    int node = blockIdx.x * 256 + tid;
    if (node >= NN) return;

    const float4* hr = (const float4*)(g_agg + (size_t)node * D);
    float acc[NC];
#pragma unroll
    for (int c = 0; c < NC; c++) acc[c] = sbm[c];

#pragma unroll
    for (int kc = 0; kc < 16; kc++) {
        float4 xv = hr[kc];
        xv.x = fmaxf(xv.x, 0.f); xv.y = fmaxf(xv.y, 0.f);
        xv.z = fmaxf(xv.z, 0.f); xv.w = fmaxf(xv.w, 0.f);
#pragma unroll
        for (int kk = 0; kk < 4; kk++) {
            float xs = (kk == 0) ? xv.x : (kk == 1) ? xv.y : (kk == 2) ? xv.z : xv.w;
            int k = kc * 4 + kk;
#pragma unroll
            for (int c = 0; c < NC; c++)
                acc[c] = fmaf(xs, sWm[k * NC + c], acc[c]);
        }
    }
    float m = acc[0];
#pragma unroll
    for (int c = 1; c < NC; c++) m = fmaxf(m, acc[c]);
    float sum = 0.f;
#pragma unroll
    for (int c = 0; c < NC; c++) { acc[c] = __expf(acc[c] - m); sum += acc[c]; }
    float inv = 1.0f / sum;
#pragma unroll
    for (int c = 0; c < NC; c++) out[(size_t)node * NC + c] = acc[c] * inv;
}

// ---------------- launch -----------------------------------------------------
extern "C" void kernel_launch(void* const* d_in, const int* in_sizes, int n_in,
                              void* d_out, int out_size) {
    const float* x  = (const float*)d_in[0];
    const int*   ei = (const int*)d_in[1];     // int32 (see note above)
    const float* w  = (const float*)d_in[2];
    const float* W1 = (const float*)d_in[3];
    const float* b1 = (const float*)d_in[4];
    const float* W2 = (const float*)d_in[5];
    const float* b2 = (const float*)d_in[6];
    const float* Wm = (const float*)d_in[7];
    const float* bm = (const float*)d_in[8];
    float* out = (float*)d_out;

    void *p_h = nullptr, *p_agg = nullptr;
    cudaGetSymbolAddress(&p_h, g_h);
    cudaGetSymbolAddress(&p_agg, g_agg);
    float* h_ptr   = (float*)p_h;
    float* agg_ptr = (float*)p_agg;

    const int T = 256;
    int gN    = (NN + T - 1) / T;
    int gE4   = (NE / 4 + T - 1) / T;    // fill: 4 edges/thread
    int gN16  = (NN * 16 + T - 1) / T;   // gather: 16 threads/node
    int gN32  = (NN * 32 + T - 1) / T;   // dinv/bnorm: 32 threads/node
    int gG    = (NN + 63) / 64;          // gemm: 4 threads/node, 64 nodes/block

    // bucket build + degrees + norms (shared by both layers)
    k_init<<<gN, T>>>();
    k_fill<<<gE4, T>>>(ei, w);
    k_dinv<<<gN32, T>>>();
    k_bnorm<<<gN32, T>>>();

    // layer 1
    k_gemm<false><<<gG, T>>>(x, W1, h_ptr);
    k_gather<<<gN16, T>>>(b1);

    // layer 2 (relu fused into gemm load)
    k_gemm<true><<<gG, T>>>(agg_ptr, W2, h_ptr);
    k_gather<<<gN16, T>>>(b2);

    // head (relu fused), softmax
    k_final<<<gN, T>>>(Wm, bm, out);
}

// round 9
// speedup vs baseline: 1.3784x; 1.3784x over previous
#include <cuda_runtime.h>
#include <cuda_bf16.h>
#include <math.h>

#define NN 50000
#define NE 800000
#define D  64
#define NC 8
#define CAP 64   // bucket capacity per node (deg ~ Poisson(16); P(>64) ~ 1e-18)

// ---------------- scratch (device globals; no allocation allowed) -----------
__device__ float g_deg[NN];                        // degree, then dinv in-place
__device__ int   g_fill[NN];                       // bucket fill counter
__device__ __align__(16) int2  g_csr[NN * CAP];    // {src, bitcast(norm)} per in-edge
__device__ __align__(16) float g_h[NN * D];        // h = X @ W
__device__ __align__(16) float g_agg[NN * D];      // aggregated output

// ---------------- init: deg = 1 (self loop), fill = 0 -----------------------
__global__ void k_init() {
    int i = blockIdx.x * blockDim.x + threadIdx.x;
    if (i < NN) { g_deg[i] = 1.0f; g_fill[i] = 0; }
}

// edge_index is int32 (JAX x64 disabled => "int64" materializes as int32)
__global__ void k_deg(const int* __restrict__ ei, const float* __restrict__ w) {
    int e = blockIdx.x * blockDim.x + threadIdx.x;
    if (e < NE) atomicAdd(&g_deg[ei[NE + e]], w[e]);
}

__global__ void k_rsqrt() {
    int i = blockIdx.x * blockDim.x + threadIdx.x;
    if (i < NN) g_deg[i] = rsqrtf(g_deg[i]);       // deg >= 1 always
}

// ---------------- CSR fill: norm + bucket placement (once, both layers) -----
__global__ void k_fill(const int* __restrict__ ei, const float* __restrict__ w) {
    int e = blockIdx.x * blockDim.x + threadIdx.x;
    if (e >= NE) return;
    int s = ei[e];
    int d = ei[NE + e];
    float nrm = g_deg[s] * w[e] * g_deg[d];
    int pos = atomicAdd(&g_fill[d], 1);
    if (pos < CAP)
        g_csr[d * CAP + pos] = make_int2(s, __float_as_int(nrm));
}

// ---------------- dense GEMM: Hout[node] = (relu?)(X[node]) @ W  ([64,64]) ---
// One thread per node, but outputs computed in TWO j-halves of 32:
//   - acc file halves (64 -> 32 regs) => ~2x occupancy vs R6's 127-reg version
//   - sW reads stay lane-uniform (warp broadcast, conflict-free)
template <bool RELU>
__global__ void __launch_bounds__(256) k_gemm(const float* __restrict__ X,
                                              const float* __restrict__ W,
                                              float* __restrict__ Hout) {
    __shared__ float4 sW[D * (D / 4)];             // [k][j4] 64x16 float4 = 16 KB
    int tid = threadIdx.x;
    for (int i = tid; i < D * (D / 4); i += 256)
        sW[i] = ((const float4*)W)[i];
    __syncthreads();

    int node = blockIdx.x * 256 + tid;
    if (node >= NN) return;

    const float4* xr = (const float4*)(X + (size_t)node * D);
    float4* ho = (float4*)(Hout + (size_t)node * D);

#pragma unroll
    for (int half = 0; half < 2; half++) {
        float4 acc[8];
#pragma unroll
        for (int j = 0; j < 8; j++) acc[j] = make_float4(0.f, 0.f, 0.f, 0.f);

#pragma unroll 4
        for (int kc = 0; kc < 16; kc++) {
            float4 xv = __ldg(&xr[kc]);            // L1-hot on the second half
            if (RELU) {
                xv.x = fmaxf(xv.x, 0.f); xv.y = fmaxf(xv.y, 0.f);
                xv.z = fmaxf(xv.z, 0.f); xv.w = fmaxf(xv.w, 0.f);
            }
#pragma unroll
            for (int kk = 0; kk < 4; kk++) {
                float xs = (kk == 0) ? xv.x : (kk == 1) ? xv.y : (kk == 2) ? xv.z : xv.w;
                int k = kc * 4 + kk;
#pragma unroll
                for (int j = 0; j < 8; j++) {
                    float4 wv = sW[k * 16 + half * 8 + j];   // lane-uniform -> broadcast
                    acc[j].x = fmaf(xs, wv.x, acc[j].x);
                    acc[j].y = fmaf(xs, wv.y, acc[j].y);
                    acc[j].z = fmaf(xs, wv.z, acc[j].z);
                    acc[j].w = fmaf(xs, wv.w, acc[j].w);
                }
            }
        }
#pragma unroll
        for (int j = 0; j < 8; j++) ho[half * 8 + j] = acc[j];
    }
}

// ---------------- gather: agg[i] = h[i]*dinv^2 + b + sum_in norm * h[src] ---
// 16 threads per node; lane j owns float4 chunk j of the 64-wide row.
__global__ void __launch_bounds__(256) k_gather(const float* __restrict__ b) {
    int tid = threadIdx.x;
    int grp = tid >> 4;
    int j = tid & 15;
    int node = blockIdx.x * 16 + grp;
    if (node >= NN) return;

    int cnt = min(g_fill[node], CAP);
    float dinv = g_deg[node];
    float d2 = dinv * dinv;

    const float4* h4 = (const float4*)g_h;
    float4 acc = h4[(size_t)node * 16 + j];        // self-loop term
    float4 bb = ((const float4*)b)[j];
    acc.x = fmaf(acc.x, d2, bb.x);
    acc.y = fmaf(acc.y, d2, bb.y);
    acc.z = fmaf(acc.z, d2, bb.z);
    acc.w = fmaf(acc.w, d2, bb.w);

    const int2* ent = g_csr + (size_t)node * CAP;
#pragma unroll 4
    for (int k = 0; k < cnt; k++) {
        int2 e = ent[k];                            // broadcast across the 16 lanes
        float nrm = __int_as_float(e.y);            // precomputed norm
        float4 v = h4[(size_t)e.x * 16 + j];        // coalesced 256B row (L2 hit)
        acc.x = fmaf(nrm, v.x, acc.x);
        acc.y = fmaf(nrm, v.y, acc.y);
        acc.z = fmaf(nrm, v.z, acc.z);
        acc.w = fmaf(nrm, v.w, acc.w);
    }
    ((float4*)g_agg)[(size_t)node * 16 + j] = acc;
}

// ---------------- head: relu -> @Wm + bm -> softmax -------------------------
__global__ void __launch_bounds__(256) k_final(const float* __restrict__ Wm,
                                               const float* __restrict__ bm,
                                               float* __restrict__ out) {
    __shared__ float sWm[D * NC];
    __shared__ float sbm[NC];
    int tid = threadIdx.x;
    for (int i = tid; i < D * NC; i += 256) sWm[i] = Wm[i];
    if (tid < NC) sbm[tid] = bm[tid];
    __syncthreads();

    int node = blockIdx.x * 256 + tid;
    if (node >= NN) return;

    const float4* hr = (const float4*)(g_agg + (size_t)node * D);
    float acc[NC];
#pragma unroll
    for (int c = 0; c < NC; c++) acc[c] = sbm[c];

#pragma unroll
    for (int kc = 0; kc < 16; kc++) {
        float4 xv = hr[kc];
        xv.x = fmaxf(xv.x, 0.f); xv.y = fmaxf(xv.y, 0.f);
        xv.z = fmaxf(xv.z, 0.f); xv.w = fmaxf(xv.w, 0.f);
#pragma unroll
        for (int kk = 0; kk < 4; kk++) {
            float xs = (kk == 0) ? xv.x : (kk == 1) ? xv.y : (kk == 2) ? xv.z : xv.w;
            int k = kc * 4 + kk;
#pragma unroll
            for (int c = 0; c < NC; c++)
                acc[c] = fmaf(xs, sWm[k * NC + c], acc[c]);
        }
    }
    float m = acc[0];
#pragma unroll
    for (int c = 1; c < NC; c++) m = fmaxf(m, acc[c]);
    float sum = 0.f;
#pragma unroll
    for (int c = 0; c < NC; c++) { acc[c] = __expf(acc[c] - m); sum += acc[c]; }
    float inv = 1.0f / sum;
#pragma unroll
    for (int c = 0; c < NC; c++) out[(size_t)node * NC + c] = acc[c] * inv;
}

// ---------------- launch -----------------------------------------------------
extern "C" void kernel_launch(void* const* d_in, const int* in_sizes, int n_in,
                              void* d_out, int out_size) {
    const float* x  = (const float*)d_in[0];
    const int*   ei = (const int*)d_in[1];     // int32 (see note above)
    const float* w  = (const float*)d_in[2];
    const float* W1 = (const float*)d_in[3];
    const float* b1 = (const float*)d_in[4];
    const float* W2 = (const float*)d_in[5];
    const float* b2 = (const float*)d_in[6];
    const float* Wm = (const float*)d_in[7];
    const float* bm = (const float*)d_in[8];
    float* out = (float*)d_out;

    void *p_h = nullptr, *p_agg = nullptr;
    cudaGetSymbolAddress(&p_h, g_h);
    cudaGetSymbolAddress(&p_agg, g_agg);
    float* h_ptr   = (float*)p_h;
    float* agg_ptr = (float*)p_agg;

    const int T = 256;
    int gN   = (NN + T - 1) / T;
    int gE   = (NE + T - 1) / T;
    int gN16 = (NN * 16 + T - 1) / T;    // gather: 16 threads/node

    // gcn_norm + CSR build (shared by both layers)
    k_init<<<gN, T>>>();
    k_deg<<<gE, T>>>(ei, w);
    k_rsqrt<<<gN, T>>>();
    k_fill<<<gE, T>>>(ei, w);

    // layer 1
    k_gemm<false><<<gN, T>>>(x, W1, h_ptr);
    k_gather<<<gN16, T>>>(b1);

    // layer 2 (relu fused into gemm load)
    k_gemm<true><<<gN, T>>>(agg_ptr, W2, h_ptr);
    k_gather<<<gN16, T>>>(b2);

    // head (relu fused), softmax
    k_final<<<gN, T>>>(Wm, bm, out);
}

// round 10
// speedup vs baseline: 1.5093x; 1.0950x over previous
#include <cuda_runtime.h>
#include <cuda_bf16.h>
#include <math.h>

#define NN 50000
#define NE 800000
#define D  64
#define NC 8
#define CAP 64   // bucket capacity per node (deg ~ Poisson(16); P(>64) ~ 1e-18)

// ---------------- scratch (device globals; no allocation allowed) -----------
__device__ float g_deg[NN];                        // degree, then dinv in-place
__device__ int   g_fill[NN];                       // bucket fill counter
__device__ __align__(16) int2  g_csr[NN * CAP];    // {src, bitcast(norm)} per in-edge
__device__ __align__(16) float g_h[NN * D];        // h = X @ W
__device__ __align__(16) float g_agg[NN * D];      // aggregated output

// ---------------- init: deg = 1 (self loop), fill = 0 -----------------------
__global__ void k_init() {
    int i = blockIdx.x * blockDim.x + threadIdx.x;
    if (i < NN) { g_deg[i] = 1.0f; g_fill[i] = 0; }
}

// edge_index is int32 (JAX x64 disabled => "int64" materializes as int32)
// 4 edges/thread; adds are result-unused -> RED (no latency chain)
__global__ void k_deg(const int* __restrict__ ei, const float* __restrict__ w) {
    int base = (blockIdx.x * blockDim.x + threadIdx.x) * 4;   // NE % 4 == 0
    if (base >= NE) return;
    int4   d4 = *(const int4*)(ei + NE + base);
    float4 w4 = *(const float4*)(w + base);
    atomicAdd(&g_deg[d4.x], w4.x);
    atomicAdd(&g_deg[d4.y], w4.y);
    atomicAdd(&g_deg[d4.z], w4.z);
    atomicAdd(&g_deg[d4.w], w4.w);
}

__global__ void k_rsqrt() {
    int i = blockIdx.x * blockDim.x + threadIdx.x;
    if (i < NN) g_deg[i] = rsqrtf(g_deg[i]);       // deg >= 1 always
}

// ---------------- CSR fill: norm + bucket, 4 edges/thread (MLP=4) -----------
__global__ void k_fill(const int* __restrict__ ei, const float* __restrict__ w) {
    int base = (blockIdx.x * blockDim.x + threadIdx.x) * 4;   // NE % 4 == 0
    if (base >= NE) return;
    int4   s4 = *(const int4*)(ei + base);
    int4   d4 = *(const int4*)(ei + NE + base);
    float4 w4 = *(const float4*)(w + base);

    float n0 = g_deg[s4.x] * w4.x * g_deg[d4.x];
    float n1 = g_deg[s4.y] * w4.y * g_deg[d4.y];
    float n2 = g_deg[s4.z] * w4.z * g_deg[d4.z];
    float n3 = g_deg[s4.w] * w4.w * g_deg[d4.w];

    int p0 = atomicAdd(&g_fill[d4.x], 1);          // 4 independent ticket chains
    int p1 = atomicAdd(&g_fill[d4.y], 1);
    int p2 = atomicAdd(&g_fill[d4.z], 1);
    int p3 = atomicAdd(&g_fill[d4.w], 1);
    if (p0 < CAP) g_csr[d4.x * CAP + p0] = make_int2(s4.x, __float_as_int(n0));
    if (p1 < CAP) g_csr[d4.y * CAP + p1] = make_int2(s4.y, __float_as_int(n1));
    if (p2 < CAP) g_csr[d4.z * CAP + p2] = make_int2(s4.z, __float_as_int(n2));
    if (p3 < CAP) g_csr[d4.w * CAP + p3] = make_int2(s4.w, __float_as_int(n3));
}

// ---------------- dense GEMM: Hout[node] = (relu?)(X[node]) @ W  ([64,64]) ---
// 256-thread block covers 128 nodes. Warps 0-3: output half q=0 (cols 0..31),
// warps 4-7: half q=1 (cols 32..63) for the SAME 128 nodes.
// q is warp-uniform => sW reads stay lane-uniform (broadcast, conflict-free).
// acc = 8 float4 = 32 regs => ~4 blocks/SM (occ ~50%) vs 16% before.
template <bool RELU>
__global__ void __launch_bounds__(256) k_gemm(const float* __restrict__ X,
                                              const float* __restrict__ W,
                                              float* __restrict__ Hout) {
    __shared__ float4 sW[D * (D / 4)];             // [k][j4] 64x16 float4 = 16 KB
    int tid = threadIdx.x;
    for (int i = tid; i < D * (D / 4); i += 256)
        sW[i] = ((const float4*)W)[i];
    __syncthreads();

    int warp = tid >> 5;
    int lane = tid & 31;
    int q = warp >> 2;                             // 0 or 1, warp-uniform
    int node = blockIdx.x * 128 + (warp & 3) * 32 + lane;
    if (node >= NN) return;

    const float4* xr = (const float4*)(X + (size_t)node * D);
    float4 acc[8];
#pragma unroll
    for (int j = 0; j < 8; j++) acc[j] = make_float4(0.f, 0.f, 0.f, 0.f);

#pragma unroll 4
    for (int kc = 0; kc < 16; kc++) {
        float4 xv = __ldg(&xr[kc]);                // q=1 warps hit L1
        if (RELU) {
            xv.x = fmaxf(xv.x, 0.f); xv.y = fmaxf(xv.y, 0.f);
            xv.z = fmaxf(xv.z, 0.f); xv.w = fmaxf(xv.w, 0.f);
        }
#pragma unroll
        for (int kk = 0; kk < 4; kk++) {
            float xs = (kk == 0) ? xv.x : (kk == 1) ? xv.y : (kk == 2) ? xv.z : xv.w;
            int k = kc * 4 + kk;
#pragma unroll
            for (int j = 0; j < 8; j++) {
                float4 wv = sW[k * 16 + q * 8 + j];   // broadcast
                acc[j].x = fmaf(xs, wv.x, acc[j].x);
                acc[j].y = fmaf(xs, wv.y, acc[j].y);
                acc[j].z = fmaf(xs, wv.z, acc[j].z);
                acc[j].w = fmaf(xs, wv.w, acc[j].w);
            }
        }
    }
    float4* ho = (float4*)(Hout + (size_t)node * D);
#pragma unroll
    for (int j = 0; j < 8; j++) ho[q * 8 + j] = acc[j];
}

// ---------------- gather: agg[i] = h[i]*dinv^2 + b + sum_in norm * h[src] ---
// 16 threads per node; lane j owns float4 chunk j of the 64-wide row.
__global__ void __launch_bounds__(256) k_gather(const float* __restrict__ b) {
    int tid = threadIdx.x;
    int grp = tid >> 4;
    int j = tid & 15;
    int node = blockIdx.x * 16 + grp;
    if (node >= NN) return;

    int cnt = min(g_fill[node], CAP);
    float dinv = g_deg[node];
    float d2 = dinv * dinv;

    const float4* h4 = (const float4*)g_h;
    float4 acc = h4[(size_t)node * 16 + j];        // self-loop term
    float4 bb = ((const float4*)b)[j];
    acc.x = fmaf(acc.x, d2, bb.x);
    acc.y = fmaf(acc.y, d2, bb.y);
    acc.z = fmaf(acc.z, d2, bb.z);
    acc.w = fmaf(acc.w, d2, bb.w);

    const int2* ent = g_csr + (size_t)node * CAP;
#pragma unroll 4
    for (int k = 0; k < cnt; k++) {
        int2 e = ent[k];                            // broadcast across the 16 lanes
        float nrm = __int_as_float(e.y);            // precomputed norm
        float4 v = h4[(size_t)e.x * 16 + j];        // coalesced 256B row (L2 hit)
        acc.x = fmaf(nrm, v.x, acc.x);
        acc.y = fmaf(nrm, v.y, acc.y);
        acc.z = fmaf(nrm, v.z, acc.z);
        acc.w = fmaf(nrm, v.w, acc.w);
    }
    ((float4*)g_agg)[(size_t)node * 16 + j] = acc;
}

// ---------------- head: relu -> @Wm + bm -> softmax -------------------------
__global__ void __launch_bounds__(256) k_final(const float* __restrict__ Wm,
                                               const float* __restrict__ bm,
                                               float* __restrict__ out) {
    __shared__ float sWm[D * NC];
    __shared__ float sbm[NC];
    int tid = threadIdx.x;
    for (int i = tid; i < D * NC; i += 256) sWm[i] = Wm[i];
    if (tid < NC) sbm[tid] = bm[tid];
    __syncthreads();

    int node = blockIdx.x * 256 + tid;
    if (node >= NN) return;

    const float4* hr = (const float4*)(g_agg + (size_t)node * D);
    float acc[NC];
#pragma unroll
    for (int c = 0; c < NC; c++) acc[c] = sbm[c];

#pragma unroll
    for (int kc = 0; kc < 16; kc++) {
        float4 xv = hr[kc];
        xv.x = fmaxf(xv.x, 0.f); xv.y = fmaxf(xv.y, 0.f);
        xv.z = fmaxf(xv.z, 0.f); xv.w = fmaxf(xv.w, 0.f);
#pragma unroll
        for (int kk = 0; kk < 4; kk++) {
            float xs = (kk == 0) ? xv.x : (kk == 1) ? xv.y : (kk == 2) ? xv.z : xv.w;
            int k = kc * 4 + kk;
#pragma unroll
            for (int c = 0; c < NC; c++)
                acc[c] = fmaf(xs, sWm[k * NC + c], acc[c]);
        }
    }
    float m = acc[0];
#pragma unroll
    for (int c = 1; c < NC; c++) m = fmaxf(m, acc[c]);
    float sum = 0.f;
#pragma unroll
    for (int c = 0; c < NC; c++) { acc[c] = __expf(acc[c] - m); sum += acc[c]; }
    float inv = 1.0f / sum;
#pragma unroll
    for (int c = 0; c < NC; c++) out[(size_t)node * NC + c] = acc[c] * inv;
}

// ---------------- launch -----------------------------------------------------
extern "C" void kernel_launch(void* const* d_in, const int* in_sizes, int n_in,
                              void* d_out, int out_size) {
    const float* x  = (const float*)d_in[0];
    const int*   ei = (const int*)d_in[1];     // int32 (see note above)
    const float* w  = (const float*)d_in[2];
    const float* W1 = (const float*)d_in[3];
    const float* b1 = (const float*)d_in[4];
    const float* W2 = (const float*)d_in[5];
    const float* b2 = (const float*)d_in[6];
    const float* Wm = (const float*)d_in[7];
    const float* bm = (const float*)d_in[8];
    float* out = (float*)d_out;

    void *p_h = nullptr, *p_agg = nullptr;
    cudaGetSymbolAddress(&p_h, g_h);
    cudaGetSymbolAddress(&p_agg, g_agg);
    float* h_ptr   = (float*)p_h;
    float* agg_ptr = (float*)p_agg;

    const int T = 256;
    int gN   = (NN + T - 1) / T;
    int gE4  = (NE / 4 + T - 1) / T;     // deg/fill: 4 edges/thread
    int gN16 = (NN * 16 + T - 1) / T;    // gather: 16 threads/node
    int gG   = (NN + 127) / 128;         // gemm: 128 nodes/block (2 warps/32-node group)

    // gcn_norm + CSR build (shared by both layers)
    k_init<<<gN, T>>>();
    k_deg<<<gE4, T>>>(ei, w);
    k_rsqrt<<<gN, T>>>();
    k_fill<<<gE4, T>>>(ei, w);

    // layer 1
    k_gemm<false><<<gG, T>>>(x, W1, h_ptr);
    k_gather<<<gN16, T>>>(b1);

    // layer 2 (relu fused into gemm load)
    k_gemm<true><<<gG, T>>>(agg_ptr, W2, h_ptr);
    k_gather<<<gN16, T>>>(b2);

    // head (relu fused), softmax
    k_final<<<gN, T>>>(Wm, bm, out);
}

// round 11
// speedup vs baseline: 1.5340x; 1.0164x over previous
#include <cuda_runtime.h>
#include <cuda_fp16.h>
#include <math.h>

#define NN 50000
#define NE 800000
#define D  64
#define NC 8
#define CAP 64   // bucket capacity per node (deg ~ Poisson(16); P(>64) ~ 1e-18)

// ---------------- scratch (device globals; no allocation allowed) -----------
__device__ float g_deg[NN];                        // degree, then dinv in-place
__device__ int   g_fill[NN];                       // bucket fill counter
__device__ __align__(16) int2   g_csr[NN * CAP];   // {src, bitcast(norm)} per in-edge
__device__ __align__(16) float  g_h[NN * D];       // h = X @ W (fp32, self-loop path)
__device__ __align__(16) __half g_h16[NN * D];     // fp16 copy (neighbor-gather path)
__device__ __align__(16) float  g_agg[NN * D];     // aggregated output

// ---------------- init: deg = 1 (self loop), fill = 0 -----------------------
__global__ void k_init() {
    int i = blockIdx.x * blockDim.x + threadIdx.x;
    if (i < NN) { g_deg[i] = 1.0f; g_fill[i] = 0; }
}

// edge_index is int32 (JAX x64 disabled => "int64" materializes as int32)
// 4 edges/thread; adds are result-unused -> RED (no latency chain)
__global__ void k_deg(const int* __restrict__ ei, const float* __restrict__ w) {
    int base = (blockIdx.x * blockDim.x + threadIdx.x) * 4;   // NE % 4 == 0
    if (base >= NE) return;
    int4   d4 = *(const int4*)(ei + NE + base);
    float4 w4 = *(const float4*)(w + base);
    atomicAdd(&g_deg[d4.x], w4.x);
    atomicAdd(&g_deg[d4.y], w4.y);
    atomicAdd(&g_deg[d4.z], w4.z);
    atomicAdd(&g_deg[d4.w], w4.w);
}

__global__ void k_rsqrt() {
    int i = blockIdx.x * blockDim.x + threadIdx.x;
    if (i < NN) g_deg[i] = rsqrtf(g_deg[i]);       // deg >= 1 always
}

// ---------------- CSR fill: 1 edge/thread (max residency wins here) ---------
__global__ void k_fill(const int* __restrict__ ei, const float* __restrict__ w) {
    int e = blockIdx.x * blockDim.x + threadIdx.x;
    if (e >= NE) return;
    int s = ei[e];
    int d = ei[NE + e];
    float nrm = g_deg[s] * w[e] * g_deg[d];
    int pos = atomicAdd(&g_fill[d], 1);
    if (pos < CAP)
        g_csr[d * CAP + pos] = make_int2(s, __float_as_int(nrm));
}

// ---------------- dense GEMM: Hout[node] = (relu?)(X[node]) @ W  ([64,64]) ---
// 256-thread block covers 128 nodes; warps 0-3 -> output half q=0, warps 4-7 ->
// q=1 (same nodes). q is warp-uniform => sW reads broadcast. Also emits fp16 h.
template <bool RELU>
__global__ void __launch_bounds__(256) k_gemm(const float* __restrict__ X,
                                              const float* __restrict__ W,
                                              float* __restrict__ Hout) {
    __shared__ float4 sW[D * (D / 4)];             // [k][j4] 64x16 float4 = 16 KB
    int tid = threadIdx.x;
    for (int i = tid; i < D * (D / 4); i += 256)
        sW[i] = ((const float4*)W)[i];
    __syncthreads();

    int warp = tid >> 5;
    int lane = tid & 31;
    int q = warp >> 2;                             // 0 or 1, warp-uniform
    int node = blockIdx.x * 128 + (warp & 3) * 32 + lane;
    if (node >= NN) return;

    const float4* xr = (const float4*)(X + (size_t)node * D);
    float4 acc[8];
#pragma unroll
    for (int j = 0; j < 8; j++) acc[j] = make_float4(0.f, 0.f, 0.f, 0.f);

#pragma unroll 4
    for (int kc = 0; kc < 16; kc++) {
        float4 xv = __ldg(&xr[kc]);                // q=1 warps hit L1
        if (RELU) {
            xv.x = fmaxf(xv.x, 0.f); xv.y = fmaxf(xv.y, 0.f);
            xv.z = fmaxf(xv.z, 0.f); xv.w = fmaxf(xv.w, 0.f);
        }
#pragma unroll
        for (int kk = 0; kk < 4; kk++) {
            float xs = (kk == 0) ? xv.x : (kk == 1) ? xv.y : (kk == 2) ? xv.z : xv.w;
            int k = kc * 4 + kk;
#pragma unroll
            for (int j = 0; j < 8; j++) {
                float4 wv = sW[k * 16 + q * 8 + j];   // broadcast
                acc[j].x = fmaf(xs, wv.x, acc[j].x);
                acc[j].y = fmaf(xs, wv.y, acc[j].y);
                acc[j].z = fmaf(xs, wv.z, acc[j].z);
                acc[j].w = fmaf(xs, wv.w, acc[j].w);
            }
        }
    }
    float4*  ho  = (float4*)(Hout + (size_t)node * D);
    __half2* ho16 = (__half2*)(g_h16 + (size_t)node * D + q * 32);
#pragma unroll
    for (int j = 0; j < 8; j++) {
        ho[q * 8 + j] = acc[j];
        ho16[2 * j]     = __floats2half2_rn(acc[j].x, acc[j].y);
        ho16[2 * j + 1] = __floats2half2_rn(acc[j].z, acc[j].w);
    }
}

// ---------------- gather: agg[i] = h32[i]*dinv^2 + b + sum_in norm*h16[src] -
// 16 threads per node; lane j owns float4 chunk j (= 4 halves in fp16 path).
__global__ void __launch_bounds__(256) k_gather(const float* __restrict__ b) {
    int tid = threadIdx.x;
    int grp = tid >> 4;
    int j = tid & 15;
    int node = blockIdx.x * 16 + grp;
    if (node >= NN) return;

    int cnt = min(g_fill[node], CAP);
    float dinv = g_deg[node];
    float d2 = dinv * dinv;

    float4 acc = ((const float4*)g_h)[(size_t)node * 16 + j];   // self term, fp32
    float4 bb = ((const float4*)b)[j];
    acc.x = fmaf(acc.x, d2, bb.x);
    acc.y = fmaf(acc.y, d2, bb.y);
    acc.z = fmaf(acc.z, d2, bb.z);
    acc.w = fmaf(acc.w, d2, bb.w);

    const int2* ent = g_csr + (size_t)node * CAP;
#pragma unroll 4
    for (int k = 0; k < cnt; k++) {
        int2 e = ent[k];                            // broadcast across the 16 lanes
        float nrm = __int_as_float(e.y);            // precomputed norm
        // fp16 row: lane j reads halves [4j..4j+4) = 8 bytes, 128B/row coalesced
        uint2 raw = *(const uint2*)(g_h16 + (size_t)e.x * D + j * 4);
        float2 f01 = __half22float2(*(const __half2*)&raw.x);
        float2 f23 = __half22float2(*(const __half2*)&raw.y);
        acc.x = fmaf(nrm, f01.x, acc.x);
        acc.y = fmaf(nrm, f01.y, acc.y);
        acc.z = fmaf(nrm, f23.x, acc.z);
        acc.w = fmaf(nrm, f23.y, acc.w);
    }
    ((float4*)g_agg)[(size_t)node * 16 + j] = acc;
}

// ---------------- head: relu -> @Wm + bm -> softmax -------------------------
__global__ void __launch_bounds__(256) k_final(const float* __restrict__ Wm,
                                               const float* __restrict__ bm,
                                               float* __restrict__ out) {
    __shared__ float sWm[D * NC];
    __shared__ float sbm[NC];
    int tid = threadIdx.x;
    for (int i = tid; i < D * NC; i += 256) sWm[i] = Wm[i];
    if (tid < NC) sbm[tid] = bm[tid];
    __syncthreads();

    int node = blockIdx.x * 256 + tid;
    if (node >= NN) return;

    const float4* hr = (const float4*)(g_agg + (size_t)node * D);
    float acc[NC];
#pragma unroll
    for (int c = 0; c < NC; c++) acc[c] = sbm[c];

#pragma unroll
    for (int kc = 0; kc < 16; kc++) {
        float4 xv = hr[kc];
        xv.x = fmaxf(xv.x, 0.f); xv.y = fmaxf(xv.y, 0.f);
        xv.z = fmaxf(xv.z, 0.f); xv.w = fmaxf(xv.w, 0.f);
#pragma unroll
        for (int kk = 0; kk < 4; kk++) {
            float xs = (kk == 0) ? xv.x : (kk == 1) ? xv.y : (kk == 2) ? xv.z : xv.w;
            int k = kc * 4 + kk;
#pragma unroll
            for (int c = 0; c < NC; c++)
                acc[c] = fmaf(xs, sWm[k * NC + c], acc[c]);
        }
    }
    float m = acc[0];
#pragma unroll
    for (int c = 1; c < NC; c++) m = fmaxf(m, acc[c]);
    float sum = 0.f;
#pragma unroll
    for (int c = 0; c < NC; c++) { acc[c] = __expf(acc[c] - m); sum += acc[c]; }
    float inv = 1.0f / sum;
#pragma unroll
    for (int c = 0; c < NC; c++) out[(size_t)node * NC + c] = acc[c] * inv;
}

// ---------------- launch -----------------------------------------------------
extern "C" void kernel_launch(void* const* d_in, const int* in_sizes, int n_in,
                              void* d_out, int out_size) {
    const float* x  = (const float*)d_in[0];
    const int*   ei = (const int*)d_in[1];     // int32 (see note above)
    const float* w  = (const float*)d_in[2];
    const float* W1 = (const float*)d_in[3];
    const float* b1 = (const float*)d_in[4];
    const float* W2 = (const float*)d_in[5];
    const float* b2 = (const float*)d_in[6];
    const float* Wm = (const float*)d_in[7];
    const float* bm = (const float*)d_in[8];
    float* out = (float*)d_out;

    void *p_h = nullptr, *p_agg = nullptr;
    cudaGetSymbolAddress(&p_h, g_h);
    cudaGetSymbolAddress(&p_agg, g_agg);
    float* h_ptr   = (float*)p_h;
    float* agg_ptr = (float*)p_agg;

    const int T = 256;
    int gN   = (NN + T - 1) / T;
    int gE   = (NE + T - 1) / T;         // fill: 1 edge/thread
    int gE4  = (NE / 4 + T - 1) / T;     // deg: 4 edges/thread
    int gN16 = (NN * 16 + T - 1) / T;    // gather: 16 threads/node
    int gG   = (NN + 127) / 128;         // gemm: 128 nodes/block

    // gcn_norm + CSR build (shared by both layers)
    k_init<<<gN, T>>>();
    k_deg<<<gE4, T>>>(ei, w);
    k_rsqrt<<<gN, T>>>();
    k_fill<<<gE, T>>>(ei, w);

    // layer 1
    k_gemm<false><<<gG, T>>>(x, W1, h_ptr);
    k_gather<<<gN16, T>>>(b1);

    // layer 2 (relu fused into gemm load)
    k_gemm<true><<<gG, T>>>(agg_ptr, W2, h_ptr);
    k_gather<<<gN16, T>>>(b2);

    // head (relu fused), softmax
    k_final<<<gN, T>>>(Wm, bm, out);
}

// round 12
// speedup vs baseline: 1.6505x; 1.0759x over previous
#include <cuda_runtime.h>
#include <cuda_fp16.h>
#include <math.h>

#define NN 50000
#define NE 800000
#define D  64
#define NC 8
#define CAP 64   // bucket capacity per node (deg ~ Poisson(16); P(>64) ~ 1e-18)

// ---------------- scratch (device globals; no allocation allowed) -----------
__device__ float g_deg[NN];                        // degree, then dinv in-place
__device__ int   g_fill[NN];                       // bucket fill counter
__device__ __align__(16) int2   g_csr[NN * CAP];   // {src, bitcast(norm)} per in-edge
__device__ __align__(16) float  g_h[NN * D];       // h = X @ W (fp32, self-loop path)
__device__ __align__(16) __half g_h16[NN * D];     // fp16 copy (neighbor-gather path)
__device__ __align__(16) float  g_agg[NN * D];     // aggregated output

// ---------------- init: deg = 1 (self loop), fill = 0 -----------------------
__global__ void k_init() {
    int i = blockIdx.x * blockDim.x + threadIdx.x;
    if (i < NN) { g_deg[i] = 1.0f; g_fill[i] = 0; }
}

// edge_index is int32 (JAX x64 disabled => "int64" materializes as int32)
// 4 edges/thread; adds are result-unused -> RED (no latency chain)
__global__ void k_deg(const int* __restrict__ ei, const float* __restrict__ w) {
    int base = (blockIdx.x * blockDim.x + threadIdx.x) * 4;   // NE % 4 == 0
    if (base >= NE) return;
    int4   d4 = *(const int4*)(ei + NE + base);
    float4 w4 = *(const float4*)(w + base);
    atomicAdd(&g_deg[d4.x], w4.x);
    atomicAdd(&g_deg[d4.y], w4.y);
    atomicAdd(&g_deg[d4.z], w4.z);
    atomicAdd(&g_deg[d4.w], w4.w);
}

__global__ void k_rsqrt() {
    int i = blockIdx.x * blockDim.x + threadIdx.x;
    if (i < NN) g_deg[i] = rsqrtf(g_deg[i]);       // deg >= 1 always
}

// ---------------- CSR fill: 1 edge/thread (max residency wins here) ---------
__global__ void k_fill(const int* __restrict__ ei, const float* __restrict__ w) {
    int e = blockIdx.x * blockDim.x + threadIdx.x;
    if (e >= NE) return;
    int s = ei[e];
    int d = ei[NE + e];
    float nrm = g_deg[s] * w[e] * g_deg[d];
    int pos = atomicAdd(&g_fill[d], 1);
    if (pos < CAP)
        g_csr[d * CAP + pos] = make_int2(s, __float_as_int(nrm));
}

// ---------------- dense GEMM: Hout[node] = (relu?)(X[node]) @ W  ([64,64]) ---
// 256-thread block covers 128 nodes; warps 0-3 -> output half q=0, warps 4-7 ->
// q=1 (same nodes). q is warp-uniform => sW reads broadcast. Also emits fp16 h.
template <bool RELU>
__global__ void __launch_bounds__(256) k_gemm(const float* __restrict__ X,
                                              const float* __restrict__ W,
                                              float* __restrict__ Hout) {
    __shared__ float4 sW[D * (D / 4)];             // [k][j4] 64x16 float4 = 16 KB
    int tid = threadIdx.x;
    for (int i = tid; i < D * (D / 4); i += 256)
        sW[i] = ((const float4*)W)[i];
    __syncthreads();

    int warp = tid >> 5;
    int lane = tid & 31;
    int q = warp >> 2;                             // 0 or 1, warp-uniform
    int node = blockIdx.x * 128 + (warp & 3) * 32 + lane;
    if (node >= NN) return;

    const float4* xr = (const float4*)(X + (size_t)node * D);
    float4 acc[8];
#pragma unroll
    for (int j = 0; j < 8; j++) acc[j] = make_float4(0.f, 0.f, 0.f, 0.f);

#pragma unroll 4
    for (int kc = 0; kc < 16; kc++) {
        float4 xv = __ldg(&xr[kc]);                // q=1 warps hit L1
        if (RELU) {
            xv.x = fmaxf(xv.x, 0.f); xv.y = fmaxf(xv.y, 0.f);
            xv.z = fmaxf(xv.z, 0.f); xv.w = fmaxf(xv.w, 0.f);
        }
#pragma unroll
        for (int kk = 0; kk < 4; kk++) {
            float xs = (kk == 0) ? xv.x : (kk == 1) ? xv.y : (kk == 2) ? xv.z : xv.w;
            int k = kc * 4 + kk;
#pragma unroll
            for (int j = 0; j < 8; j++) {
                float4 wv = sW[k * 16 + q * 8 + j];   // broadcast
                acc[j].x = fmaf(xs, wv.x, acc[j].x);
                acc[j].y = fmaf(xs, wv.y, acc[j].y);
                acc[j].z = fmaf(xs, wv.z, acc[j].z);
                acc[j].w = fmaf(xs, wv.w, acc[j].w);
            }
        }
    }
    float4*  ho  = (float4*)(Hout + (size_t)node * D);
    __half2* ho16 = (__half2*)(g_h16 + (size_t)node * D + q * 32);
#pragma unroll
    for (int j = 0; j < 8; j++) {
        ho[q * 8 + j] = acc[j];
        ho16[2 * j]     = __floats2half2_rn(acc[j].x, acc[j].y);
        ho16[2 * j + 1] = __floats2half2_rn(acc[j].z, acc[j].w);
    }
}

// ---------------- gather: agg[i] = h32[i]*dinv^2 + b + sum_in norm*h16[src] -
// 16 threads per node; lane j owns float4 chunk j (= 4 halves in fp16 path).
__global__ void __launch_bounds__(256) k_gather(const float* __restrict__ b) {
    int tid = threadIdx.x;
    int grp = tid >> 4;
    int j = tid & 15;
    int node = blockIdx.x * 16 + grp;
    if (node >= NN) return;

    int cnt = min(g_fill[node], CAP);
    float dinv = g_deg[node];
    float d2 = dinv * dinv;

    float4 acc = ((const float4*)g_h)[(size_t)node * 16 + j];   // self term, fp32
    float4 bb = ((const float4*)b)[j];
    acc.x = fmaf(acc.x, d2, bb.x);
    acc.y = fmaf(acc.y, d2, bb.y);
    acc.z = fmaf(acc.z, d2, bb.z);
    acc.w = fmaf(acc.w, d2, bb.w);

    const int2* ent = g_csr + (size_t)node * CAP;
#pragma unroll 4
    for (int k = 0; k < cnt; k++) {
        int2 e = ent[k];                            // broadcast across the 16 lanes
        float nrm = __int_as_float(e.y);            // precomputed norm
        // fp16 row: lane j reads halves [4j..4j+4) = 8 bytes, 128B/row coalesced
        uint2 raw = *(const uint2*)(g_h16 + (size_t)e.x * D + j * 4);
        float2 f01 = __half22float2(*(const __half2*)&raw.x);
        float2 f23 = __half22float2(*(const __half2*)&raw.y);
        acc.x = fmaf(nrm, f01.x, acc.x);
        acc.y = fmaf(nrm, f01.y, acc.y);
        acc.z = fmaf(nrm, f23.x, acc.z);
        acc.w = fmaf(nrm, f23.y, acc.w);
    }
    ((float4*)g_agg)[(size_t)node * 16 + j] = acc;
}

// ---------------- head: relu -> @Wm + bm -> softmax -------------------------
__global__ void __launch_bounds__(256) k_final(const float* __restrict__ Wm,
                                               const float* __restrict__ bm,
                                               float* __restrict__ out) {
    __shared__ float sWm[D * NC];
    __shared__ float sbm[NC];
    int tid = threadIdx.x;
    for (int i = tid; i < D * NC; i += 256) sWm[i] = Wm[i];
    if (tid < NC) sbm[tid] = bm[tid];
    __syncthreads();

    int node = blockIdx.x * 256 + tid;
    if (node >= NN) return;

    const float4* hr = (const float4*)(g_agg + (size_t)node * D);
    float acc[NC];
#pragma unroll
    for (int c = 0; c < NC; c++) acc[c] = sbm[c];

#pragma unroll
    for (int kc = 0; kc < 16; kc++) {
        float4 xv = hr[kc];
        xv.x = fmaxf(xv.x, 0.f); xv.y = fmaxf(xv.y, 0.f);
        xv.z = fmaxf(xv.z, 0.f); xv.w = fmaxf(xv.w, 0.f);
#pragma unroll
        for (int kk = 0; kk < 4; kk++) {
            float xs = (kk == 0) ? xv.x : (kk == 1) ? xv.y : (kk == 2) ? xv.z : xv.w;
            int k = kc * 4 + kk;
#pragma unroll
            for (int c = 0; c < NC; c++)
                acc[c] = fmaf(xs, sWm[k * NC + c], acc[c]);
        }
    }
    float m = acc[0];
#pragma unroll
    for (int c = 1; c < NC; c++) m = fmaxf(m, acc[c]);
    float sum = 0.f;
#pragma unroll
    for (int c = 0; c < NC; c++) { acc[c] = __expf(acc[c] - m); sum += acc[c]; }
    float inv = 1.0f / sum;
#pragma unroll
    for (int c = 0; c < NC; c++) out[(size_t)node * NC + c] = acc[c] * inv;
}

// ---------------- launch -----------------------------------------------------
// Layer-1 GEMM depends only on (x, W1): run it on a side stream, overlapped
// with the prep chain (init -> deg -> rsqrt -> fill). Event fork/join is
// graph-capture legal. Stream/events are created on the FIRST call (the
// correctness run, outside capture) and reused; work is identical every call.
extern "C" void kernel_launch(void* const* d_in, const int* in_sizes, int n_in,
                              void* d_out, int out_size) {
    const float* x  = (const float*)d_in[0];
    const int*   ei = (const int*)d_in[1];     // int32 (see note above)
    const float* w  = (const float*)d_in[2];
    const float* W1 = (const float*)d_in[3];
    const float* b1 = (const float*)d_in[4];
    const float* W2 = (const float*)d_in[5];
    const float* b2 = (const float*)d_in[6];
    const float* Wm = (const float*)d_in[7];
    const float* bm = (const float*)d_in[8];
    float* out = (float*)d_out;

    void *p_h = nullptr, *p_agg = nullptr;
    cudaGetSymbolAddress(&p_h, g_h);
    cudaGetSymbolAddress(&p_agg, g_agg);
    float* h_ptr   = (float*)p_h;
    float* agg_ptr = (float*)p_agg;

    static cudaStream_t s_side = nullptr;
    static cudaEvent_t  s_evFork = nullptr, s_evG1 = nullptr;
    if (s_side == nullptr) {                       // first call = correctness run (not captured)
        cudaStreamCreateWithFlags(&s_side, cudaStreamNonBlocking);
        cudaEventCreateWithFlags(&s_evFork, cudaEventDisableTiming);
        cudaEventCreateWithFlags(&s_evG1, cudaEventDisableTiming);
    }

    const int T = 256;
    int gN   = (NN + T - 1) / T;
    int gE   = (NE + T - 1) / T;         // fill: 1 edge/thread
    int gE4  = (NE / 4 + T - 1) / T;     // deg: 4 edges/thread
    int gN16 = (NN * 16 + T - 1) / T;    // gather: 16 threads/node
    int gG   = (NN + 127) / 128;         // gemm: 128 nodes/block

    // fork: layer-1 GEMM on side stream, concurrent with prep chain
    cudaEventRecord(s_evFork, 0);
    cudaStreamWaitEvent(s_side, s_evFork, 0);
    k_gemm<false><<<gG, T, 0, s_side>>>(x, W1, h_ptr);
    cudaEventRecord(s_evG1, s_side);

    // prep chain on default stream (shared by both layers)
    k_init<<<gN, T>>>();
    k_deg<<<gE4, T>>>(ei, w);
    k_rsqrt<<<gN, T>>>();
    k_fill<<<gE, T>>>(ei, w);

    // join: gather1 needs fill (default) + gemm1 (side)
    cudaStreamWaitEvent(0, s_evG1, 0);
    k_gather<<<gN16, T>>>(b1);

    // layer 2 (relu fused into gemm load)
    k_gemm<true><<<gG, T>>>(agg_ptr, W2, h_ptr);
    k_gather<<<gN16, T>>>(b2);

    // head (relu fused), softmax
    k_final<<<gN, T>>>(Wm, bm, out);
}